// round 2
// baseline (speedup 1.0000x reference)
#include <cuda_runtime.h>
#include <cuda_bf16.h>

// ---------------------------------------------------------------------------
// Fused single-kernel hypernetwork. Only live computation:
//   70 dot products of length 6400 (w3 rows i*64 w/ W2 col 1; w4 rows
//   floor(k*2048/3) w/ W2 cols {65,69,67,...}), scalar relu chains, then
//   out = [tile(relu(h3 o W3b+b3b),80) | 64 zeros | relu(h4 o W4b+b4b)].
// Grid barrier is deadlock-free: 404 blocks all co-resident in wave 1.
// ---------------------------------------------------------------------------

#define NROW   70
#define NCHUNK 5
#define NPROD  (NROW * NCHUNK)   // 350 producer blocks
#define NBLK   404               // total blocks (>= ceil(103186/256))
#define SEG3_END  409600
#define ZERO_END  409664
#define OUT_TOTAL 412742

__device__ float g_part[NROW * NCHUNK];
__device__ int   g_ctr;    // producer arrivals (zero at module load; reset each run)
__device__ int   g_done;   // block completions (for reset)

__device__ __forceinline__ float frelu(float v) { return fmaxf(v, 0.f); }

__global__ __launch_bounds__(256, 8)
void fused_kernel(const float* __restrict__ inp,
                  const float* __restrict__ W1,
                  const float* __restrict__ b1,
                  const float* __restrict__ W2,
                  const float* __restrict__ b2,
                  const float* __restrict__ W3a,
                  const float* __restrict__ b3a,
                  const float* __restrict__ W3b,
                  const float* __restrict__ b3b,
                  const float* __restrict__ W4a,
                  const float* __restrict__ b4a,
                  const float* __restrict__ W4b,
                  const float* __restrict__ b4b,
                  float* __restrict__ out) {
    const int bid = blockIdx.x;
    const int tid = threadIdx.x;

    // ------------------------------------------------------------------
    // Phase 0 (all blocks): prefetch output-phase operands into registers.
    // These are independent of the hidden values, so their DRAM latency
    // overlaps the producer phase entirely.
    // ------------------------------------------------------------------
    const int o4 = bid * 256 + tid;      // float4 group index
    const int o  = o4 * 4;

    float wA0 = 0.f, wA1 = 0.f, wA2 = 0.f, wA3 = 0.f;
    float bA0 = 0.f, bA1 = 0.f, bA2 = 0.f, bA3 = 0.f;
    int   hIdx = -1;                     // seg3: one h index for all 4 lanes
    int   h0 = -1, h1 = -1, h2 = -1, h3 = -1;  // tail per-lane h indices

    const bool seg3 = (o < SEG3_END);
    if (seg3) {
        int q4 = o4 % 1280;              // float4 index within one 5120 tile
        hIdx   = q4 / 20;                // 20 float4 per hidden scalar (80 floats)
        int k4 = q4 % 20;
        float4 wq = ((const float4*)W3b)[k4];
        float4 bq = ((const float4*)b3b)[k4];
        wA0 = wq.x; wA1 = wq.y; wA2 = wq.z; wA3 = wq.w;
        bA0 = bq.x; bA1 = bq.y; bA2 = bq.z; bA3 = bq.w;
    } else if (o < OUT_TOTAL) {
        #pragma unroll
        for (int l = 0; l < 4; l++) {
            int e = o + l;
            float wv = 0.f, bv = 0.f; int hv = -1;
            if (e >= ZERO_END && e < OUT_TOTAL) {
                int p  = e - ZERO_END;
                int i4 = p / 513;
                int k  = p - i4 * 513;
                wv = W4b[k]; bv = b4b[k]; hv = 64 + i4;
            }
            if (l == 0) { wA0 = wv; bA0 = bv; h0 = hv; }
            if (l == 1) { wA1 = wv; bA1 = bv; h1 = hv; }
            if (l == 2) { wA2 = wv; bA2 = bv; h2 = hv; }
            if (l == 3) { wA3 = wv; bA3 = bv; h3 = hv; }
        }
    }

    // ------------------------------------------------------------------
    // Phase 1 (blocks 0..349): partial dot products.
    // Block b: row i = b/5, chunk c = b%5 covering float4 [c*320, c*320+320).
    // ------------------------------------------------------------------
    if (bid < NPROD) {
        const int i = bid / NCHUNK;
        const int c = bid - i * NCHUNK;
        const int row = (i < 64) ? (i * 64) : (((i - 64) * 2048) / 3);

        const float4* __restrict__ ip = (const float4*)(inp + (size_t)row * 6400);
        const float4* __restrict__ wp = (const float4*)W1;

        const int j = c * 320 + tid;
        float4 a0 = ip[j];
        float4 w0 = wp[j];
        float sum = a0.x * w0.x + a0.y * w0.y + a0.z * w0.z + a0.w * w0.w;
        if (tid < 64) {
            float4 a1 = ip[j + 256];
            float4 w1 = wp[j + 256];
            sum += a1.x * w1.x + a1.y * w1.y + a1.z * w1.z + a1.w * w1.w;
        }

        #pragma unroll
        for (int off = 16; off; off >>= 1)
            sum += __shfl_down_sync(0xffffffffu, sum, off);

        __shared__ float ws[8];
        if ((tid & 31) == 0) ws[tid >> 5] = sum;
        __syncthreads();
        if (tid == 0) {
            float t = 0.f;
            #pragma unroll
            for (int w = 0; w < 8; w++) t += ws[w];
            g_part[i * NCHUNK + c] = t;
            __threadfence();
            atomicAdd(&g_ctr, 1);
        }
    }

    // ------------------------------------------------------------------
    // Grid barrier: wait for all 350 partials.
    // ------------------------------------------------------------------
    if (tid == 0) {
        volatile int* c = &g_ctr;
        while (*c < NPROD) __nanosleep(64);
    }
    __syncthreads();

    // ------------------------------------------------------------------
    // Phase 2: fold partials + scalar relu chain into smem h[70].
    // ------------------------------------------------------------------
    __shared__ float hs[NROW];
    if (tid < NROW) {
        float t = 0.f;
        #pragma unroll
        for (int c = 0; c < NCHUNK; c++)
            t += __ldcg(&g_part[tid * NCHUNK + c]);

        float s = frelu(t + b1[0]);                       // layer 1
        int col;
        if (tid < 64) col = 1;
        else {
            int m = (tid - 64) % 3;                       // cols 65,69,67 repeating
            col = (m == 0) ? 65 : (m == 1) ? 69 : 67;
        }
        float x = frelu(fmaf(s, W2[col], b2[col]));       // layer 2
        float h = (tid < 64) ? frelu(fmaf(x, W3a[0], b3a[0]))
                             : frelu(fmaf(x, W4a[0], b4a[0]));
        hs[tid] = h;
    }
    __syncthreads();

    // ------------------------------------------------------------------
    // Phase 3: emit outputs (operands already in registers).
    // ------------------------------------------------------------------
    if (seg3) {
        float h = hs[hIdx];
        float4 r;
        r.x = frelu(fmaf(h, wA0, bA0));
        r.y = frelu(fmaf(h, wA1, bA1));
        r.z = frelu(fmaf(h, wA2, bA2));
        r.w = frelu(fmaf(h, wA3, bA3));
        *(float4*)(out + o) = r;
    } else if (o < OUT_TOTAL) {
        if (o + 0 < OUT_TOTAL) out[o + 0] = (h0 < 0) ? 0.f : frelu(fmaf(hs[h0], wA0, bA0));
        if (o + 1 < OUT_TOTAL) out[o + 1] = (h1 < 0) ? 0.f : frelu(fmaf(hs[h1], wA1, bA1));
        if (o + 2 < OUT_TOTAL) out[o + 2] = (h2 < 0) ? 0.f : frelu(fmaf(hs[h2], wA2, bA2));
        if (o + 3 < OUT_TOTAL) out[o + 3] = (h3 < 0) ? 0.f : frelu(fmaf(hs[h3], wA3, bA3));
    }

    // ------------------------------------------------------------------
    // Reset counters for next graph replay (last block to finish).
    // Every block increments g_done only after passing the spin barrier,
    // so the reset can never race a spinning reader.
    // ------------------------------------------------------------------
    if (tid == 0) {
        int old = atomicAdd(&g_done, 1);
        if (old == NBLK - 1) {
            g_ctr  = 0;
            g_done = 0;
            __threadfence();
        }
    }
}

extern "C" void kernel_launch(void* const* d_in, const int* in_sizes, int n_in,
                              void* d_out, int out_size) {
    const float* inp = (const float*)d_in[0];
    const float* W1  = (const float*)d_in[1];
    const float* b1  = (const float*)d_in[2];
    const float* W2  = (const float*)d_in[3];
    const float* b2  = (const float*)d_in[4];
    const float* W3a = (const float*)d_in[5];
    const float* b3a = (const float*)d_in[6];
    const float* W3b = (const float*)d_in[7];
    const float* b3b = (const float*)d_in[8];
    const float* W4a = (const float*)d_in[9];
    const float* b4a = (const float*)d_in[10];
    const float* W4b = (const float*)d_in[11];
    const float* b4b = (const float*)d_in[12];
    float* out = (float*)d_out;

    fused_kernel<<<NBLK, 256>>>(inp, W1, b1, W2, b2, W3a, b3a,
                                W3b, b3b, W4a, b4a, W4b, b4b, out);
}

// round 3
// speedup vs baseline: 1.5000x; 1.5000x over previous
#include <cuda_runtime.h>
#include <cuda_bf16.h>

// ---------------------------------------------------------------------------
// Two kernels overlapped via Programmatic Dependent Launch (PDL).
// Live computation only:
//   70 dot products of length 6400 (w3: batch rows i*64, W2 col 1;
//   w4: rows floor(k*2048/3), W2 cols {65,69,67,...}), scalar relu chains,
//   out = [tile(relu(h3 o W3b+b3b), 80) | 64 zeros | relu(h4 o W4b+b4b)].
// ---------------------------------------------------------------------------

#define NROW   70
#define NCHUNK 5
#define NPROD  (NROW * NCHUNK)   // 350 producer blocks
#define SEG3_END  409600
#define ZERO_END  409664
#define OUT_TOTAL 412742
#define OUT_BLOCKS 404           // ceil(103186 groups / 256)

__device__ float g_part[NROW * NCHUNK];

__device__ __forceinline__ float frelu(float v) { return fmaxf(v, 0.f); }

// ---------------------------------------------------------------------------
// Kernel 1: partial dot products. Block b -> row i=b/5, chunk c=b%5.
// 320 threads, exactly one float4 of inp and W1 each.
// ---------------------------------------------------------------------------
__global__ __launch_bounds__(320)
void partial_kernel(const float* __restrict__ inp,
                    const float* __restrict__ W1) {
    // Let the dependent kernel begin its launch/prefetch right away.
    cudaTriggerProgrammaticLaunchCompletion();

    const int bid = blockIdx.x;
    const int tid = threadIdx.x;
    const int i = bid / NCHUNK;
    const int c = bid - i * NCHUNK;
    const int row = (i < 64) ? (i * 64) : (((i - 64) * 2048) / 3);

    const float4* __restrict__ ip = (const float4*)(inp + (size_t)row * 6400);
    const float4* __restrict__ wp = (const float4*)W1;

    const int j = c * 320 + tid;
    float4 a = ip[j];
    float4 w = wp[j];
    float sum = a.x * w.x + a.y * w.y + a.z * w.z + a.w * w.w;

    #pragma unroll
    for (int off = 16; off; off >>= 1)
        sum += __shfl_down_sync(0xffffffffu, sum, off);

    __shared__ float ws[10];
    if ((tid & 31) == 0) ws[tid >> 5] = sum;
    __syncthreads();
    if (tid == 0) {
        float t = 0.f;
        #pragma unroll
        for (int q = 0; q < 10; q++) t += ws[q];
        g_part[i * NCHUNK + c] = t;
    }
}

// ---------------------------------------------------------------------------
// Kernel 2 (PDL secondary): prefetch independent operands, wait for kernel 1,
// fold partials + scalar relu chain, emit outputs.
// ---------------------------------------------------------------------------
__global__ __launch_bounds__(256)
void output_kernel(const float* __restrict__ b1,
                   const float* __restrict__ W2,
                   const float* __restrict__ b2,
                   const float* __restrict__ W3a,
                   const float* __restrict__ b3a,
                   const float* __restrict__ W3b,
                   const float* __restrict__ b3b,
                   const float* __restrict__ W4a,
                   const float* __restrict__ b4a,
                   const float* __restrict__ W4b,
                   const float* __restrict__ b4b,
                   float* __restrict__ out) {
    const int bid = blockIdx.x;
    const int tid = threadIdx.x;
    const int o4 = bid * 256 + tid;
    const int o  = o4 * 4;

    // --- Prefetch (independent of kernel 1) -------------------------------
    float wA0 = 0.f, wA1 = 0.f, wA2 = 0.f, wA3 = 0.f;
    float bA0 = 0.f, bA1 = 0.f, bA2 = 0.f, bA3 = 0.f;
    int   hIdx = -1;
    int   h0 = -1, h1 = -1, h2 = -1, h3 = -1;

    const bool seg3 = (o < SEG3_END);
    if (seg3) {
        int q4 = o4 % 1280;          // float4 index within one 5120-float tile
        hIdx   = q4 / 20;            // 20 float4 per hidden scalar
        int k4 = q4 % 20;
        float4 wq = ((const float4*)W3b)[k4];
        float4 bq = ((const float4*)b3b)[k4];
        wA0 = wq.x; wA1 = wq.y; wA2 = wq.z; wA3 = wq.w;
        bA0 = bq.x; bA1 = bq.y; bA2 = bq.z; bA3 = bq.w;
    } else if (o < OUT_TOTAL) {
        #pragma unroll
        for (int l = 0; l < 4; l++) {
            int e = o + l;
            float wv = 0.f, bv = 0.f; int hv = -1;
            if (e >= ZERO_END && e < OUT_TOTAL) {
                int p  = e - ZERO_END;
                int i4 = p / 513;
                int k  = p - i4 * 513;
                wv = W4b[k]; bv = b4b[k]; hv = 64 + i4;
            }
            if (l == 0) { wA0 = wv; bA0 = bv; h0 = hv; }
            if (l == 1) { wA1 = wv; bA1 = bv; h1 = hv; }
            if (l == 2) { wA2 = wv; bA2 = bv; h2 = hv; }
            if (l == 3) { wA3 = wv; bA3 = bv; h3 = hv; }
        }
    }

    // Scalar-chain operands for the fold (also independent of kernel 1).
    float c_b1 = 0.f, c_W2 = 0.f, c_b2 = 0.f, c_wa = 0.f, c_ba = 0.f;
    if (tid < NROW) {
        int col;
        if (tid < 64) col = 1;
        else {
            int m = (tid - 64) % 3;              // 65, 69, 67 repeating
            col = (m == 0) ? 65 : (m == 1) ? 69 : 67;
        }
        c_b1 = b1[0];
        c_W2 = W2[col];
        c_b2 = b2[col];
        c_wa = (tid < 64) ? W3a[0] : W4a[0];
        c_ba = (tid < 64) ? b3a[0] : b4a[0];
    }

    // --- Wait for kernel 1's memory to be visible -------------------------
    cudaGridDependencySynchronize();

    // --- Fold partials + relu chain into smem hs[70] ----------------------
    __shared__ float hs[NROW];
    if (tid < NROW) {
        float t = 0.f;
        #pragma unroll
        for (int c = 0; c < NCHUNK; c++)
            t += __ldcg(&g_part[tid * NCHUNK + c]);
        float s = frelu(t + c_b1);
        float x = frelu(fmaf(s, c_W2, c_b2));
        hs[tid] = frelu(fmaf(x, c_wa, c_ba));
    }
    __syncthreads();

    // --- Emit outputs -----------------------------------------------------
    if (seg3) {
        float h = hs[hIdx];
        float4 r;
        r.x = frelu(fmaf(h, wA0, bA0));
        r.y = frelu(fmaf(h, wA1, bA1));
        r.z = frelu(fmaf(h, wA2, bA2));
        r.w = frelu(fmaf(h, wA3, bA3));
        *(float4*)(out + o) = r;
    } else if (o < OUT_TOTAL) {
        if (o + 0 < OUT_TOTAL) out[o + 0] = (h0 < 0) ? 0.f : frelu(fmaf(hs[h0], wA0, bA0));
        if (o + 1 < OUT_TOTAL) out[o + 1] = (h1 < 0) ? 0.f : frelu(fmaf(hs[h1], wA1, bA1));
        if (o + 2 < OUT_TOTAL) out[o + 2] = (h2 < 0) ? 0.f : frelu(fmaf(hs[h2], wA2, bA2));
        if (o + 3 < OUT_TOTAL) out[o + 3] = (h3 < 0) ? 0.f : frelu(fmaf(hs[h3], wA3, bA3));
    }
}

extern "C" void kernel_launch(void* const* d_in, const int* in_sizes, int n_in,
                              void* d_out, int out_size) {
    const float* inp = (const float*)d_in[0];
    const float* W1  = (const float*)d_in[1];
    const float* b1  = (const float*)d_in[2];
    const float* W2  = (const float*)d_in[3];
    const float* b2  = (const float*)d_in[4];
    const float* W3a = (const float*)d_in[5];
    const float* b3a = (const float*)d_in[6];
    const float* W3b = (const float*)d_in[7];
    const float* b3b = (const float*)d_in[8];
    const float* W4a = (const float*)d_in[9];
    const float* b4a = (const float*)d_in[10];
    const float* W4b = (const float*)d_in[11];
    const float* b4b = (const float*)d_in[12];
    float* out = (float*)d_out;

    // Kernel 1: plain launch on the capture (default) stream.
    partial_kernel<<<NPROD, 320>>>(inp, W1);

    // Kernel 2: PDL secondary — launch overlaps kernel 1's execution;
    // cudaGridDependencySynchronize() inside provides the ordering.
    cudaLaunchConfig_t cfg = {};
    cfg.gridDim  = dim3(OUT_BLOCKS);
    cfg.blockDim = dim3(256);
    cfg.dynamicSmemBytes = 0;
    cfg.stream = 0;
    cudaLaunchAttribute attr[1];
    attr[0].id = cudaLaunchAttributeProgrammaticStreamSerialization;
    attr[0].val.programmaticStreamSerializationAllowed = 1;
    cfg.attrs = attr;
    cfg.numAttrs = 1;
    cudaLaunchKernelEx(&cfg, output_kernel,
                       b1, W2, b2, W3a, b3a, W3b, b3b, W4a, b4a, W4b, b4b, out);
}